// round 8
// baseline (speedup 1.0000x reference)
#include <cuda_runtime.h>
#include <cstdint>
#include <cstddef>

#define FEAT 128
#define NUM_BASES 4
#define NCT 5
#define MAX_NODES 100000
#define MAX_EDGES 1000000

typedef unsigned int u32;

// scratch
__device__ float g_proj[(size_t)MAX_NODES * NUM_BASES * FEAT];
__device__ float g_wt[NCT * FEAT * FEAT];      // [ct][n][k] = W_ct[k][n]
__device__ int   g_cnt[MAX_NODES + 1];
__device__ int   g_off[MAX_NODES + 1];
__device__ int   g_pos[MAX_NODES + 1];
__device__ int   g_pk[MAX_EDGES];              // (src<<3)|rel, dst-sorted

__device__ __forceinline__ u32 tf32r(float x) {
    u32 r; asm("cvt.rna.tf32.f32 %0, %1;" : "=r"(r) : "f"(x)); return r;
}
__device__ __forceinline__ void mma_tf32(float* d, const u32* a, const u32* b) {
    asm("mma.sync.aligned.m16n8k8.row.col.f32.tf32.tf32.f32 "
        "{%0,%1,%2,%3}, {%4,%5,%6,%7}, {%8,%9}, {%0,%1,%2,%3};"
        : "+f"(d[0]), "+f"(d[1]), "+f"(d[2]), "+f"(d[3])
        : "r"(a[0]), "r"(a[1]), "r"(a[2]), "r"(a[3]), "r"(b[0]), "r"(b[1]));
}
__device__ __forceinline__ u32 smem_u32(const void* p) {
    u32 a;
    asm("{ .reg .u64 t; cvta.to.shared.u64 t, %1; cvt.u32.u64 %0, t; }" : "=r"(a) : "l"(p));
    return a;
}
__device__ __forceinline__ void ldsm4(u32& r0, u32& r1, u32& r2, u32& r3, u32 addr) {
    asm volatile("ldmatrix.sync.aligned.m8n8.x4.shared.b16 {%0,%1,%2,%3}, [%4];"
                 : "=r"(r0), "=r"(r1), "=r"(r2), "=r"(r3) : "r"(addr));
}

// ---------------- kernel 0: transpose weights into g_wt ----------------
__global__ void transpose_w_kernel(const float* __restrict__ weight,
                                   const float* __restrict__ root)
{
    __shared__ float tile[32][33];
    const int ct = blockIdx.z;
    const float* __restrict__ src = (ct < NUM_BASES) ? (weight + (size_t)ct * FEAT * FEAT)
                                                     : root;
    const int n0 = blockIdx.x * 32, k0 = blockIdx.y * 32;
    const int tx = threadIdx.x, ty = threadIdx.y;  // 32 x 8
#pragma unroll
    for (int j = 0; j < 32; j += 8)
        tile[ty + j][tx] = src[(size_t)(k0 + ty + j) * FEAT + n0 + tx];
    __syncthreads();
    float* __restrict__ dst = g_wt + (size_t)ct * FEAT * FEAT;
#pragma unroll
    for (int j = 0; j < 32; j += 8)
        dst[(size_t)(n0 + ty + j) * FEAT + k0 + tx] = tile[tx][ty + j];
}

// ---------------- dst-CSR build ----------------
__global__ void zero_cnt_kernel(int n)
{
    int i = blockIdx.x * blockDim.x + threadIdx.x;
    if (i <= n) g_cnt[i] = 0;
}
__global__ void hist_kernel(const int* __restrict__ dst, int n_edges)
{
    int i = blockIdx.x * blockDim.x + threadIdx.x;
    if (i < n_edges) atomicAdd(&g_cnt[dst[i]], 1);
}
// single-block carry scan over n+1 counters (exclusive)
__global__ void scan_kernel(int n)   // n = n_nodes + 1 elements
{
    __shared__ int tmp[1024];
    const int t = threadIdx.x;
    int carry = 0;
    for (int base = 0; base < n; base += 1024) {
        const int i = base + t;
        const int v = (i < n) ? g_cnt[i] : 0;
        tmp[t] = v;
        __syncthreads();
        for (int d = 1; d < 1024; d <<= 1) {
            int x = (t >= d) ? tmp[t - d] : 0;
            __syncthreads();
            tmp[t] += x;
            __syncthreads();
        }
        if (i < n) {
            const int excl = carry + tmp[t] - v;
            g_off[i] = excl;
            g_pos[i] = excl;
        }
        carry += tmp[1023];
        __syncthreads();
    }
}
__global__ void scatter_kernel(const int* __restrict__ src,
                               const int* __restrict__ dst,
                               const int* __restrict__ rel, int n_edges)
{
    int i = blockIdx.x * blockDim.x + threadIdx.x;
    if (i >= n_edges) return;
    const int pos = atomicAdd(&g_pos[dst[i]], 1);
    g_pk[pos] = (src[i] << 3) | rel[i];
}

// ---------------- kernel 1: split-TF32 mma.sync GEMM (R5, best) ----------------
#define BK 32
#define PAD 36
#define TILE_F (128 * PAD)
#define SM_TOTALB (4 * TILE_F * 4)   // 73728 B -> 2 blocks/SM

__global__ void __launch_bounds__(256, 2)
rgcn_gemm_mma_kernel(const float* __restrict__ h,
                     const float* __restrict__ bias,
                     float* __restrict__ out, int n_nodes)
{
    extern __shared__ float smem[];
    float* As_hi = smem;
    float* As_lo = smem + TILE_F;
    float* Bs_hi = smem + 2 * TILE_F;
    float* Bs_lo = smem + 3 * TILE_F;

    const int tid  = threadIdx.x;
    const int lane = tid & 31;
    const int w    = tid >> 5;
    const int g    = lane >> 2;
    const int tig  = lane & 3;
    const int warp_m = w & 3;
    const int warp_n = w >> 2;

    const int ct   = blockIdx.y;
    const int row0 = blockIdx.x * 128;
    const float* __restrict__ Bsrc = g_wt + (size_t)ct * FEAT * FEAT;

    const int a_row_in = lane & 15;
    const int a_kd     = (lane >> 4) * 4;
    const int b_row_in = (lane & 7) + ((lane >> 4) << 3);
    const int b_kd     = ((lane & 15) >> 3) * 4;

    const u32 sAhi = smem_u32(As_hi), sAlo = smem_u32(As_lo);
    const u32 sBhi = smem_u32(Bs_hi), sBlo = smem_u32(Bs_lo);

    float acc[2][8][4];
#pragma unroll
    for (int mi = 0; mi < 2; mi++)
#pragma unroll
        for (int j = 0; j < 8; j++)
#pragma unroll
            for (int c = 0; c < 4; c++) acc[mi][j][c] = 0.f;

    for (int kc = 0; kc < FEAT; kc += BK) {
#pragma unroll
        for (int i = 0; i < 4; i++) {
            const int v  = tid + i * 256;
            const int r  = v >> 3;
            const int c4 = (v & 7) * 4;
            float4 av = make_float4(0.f, 0.f, 0.f, 0.f);
            const int gr = row0 + r;
            if (gr < n_nodes)
                av = *(const float4*)(h + (size_t)gr * FEAT + kc + c4);
            u32 hi[4]; float lo[4];
#pragma unroll
            for (int e = 0; e < 4; e++) {
                float x = (&av.x)[e];
                hi[e] = tf32r(x);
                lo[e] = x - __uint_as_float(hi[e]);
            }
            *(uint4*)(As_hi + r * PAD + c4) = make_uint4(hi[0], hi[1], hi[2], hi[3]);
            *(uint4*)(As_lo + r * PAD + c4) = make_uint4(tf32r(lo[0]), tf32r(lo[1]),
                                                         tf32r(lo[2]), tf32r(lo[3]));
            float4 bv = *(const float4*)(Bsrc + (size_t)r * FEAT + kc + c4);
#pragma unroll
            for (int e = 0; e < 4; e++) {
                float x = (&bv.x)[e];
                hi[e] = tf32r(x);
                lo[e] = x - __uint_as_float(hi[e]);
            }
            *(uint4*)(Bs_hi + r * PAD + c4) = make_uint4(hi[0], hi[1], hi[2], hi[3]);
            *(uint4*)(Bs_lo + r * PAD + c4) = make_uint4(tf32r(lo[0]), tf32r(lo[1]),
                                                         tf32r(lo[2]), tf32r(lo[3]));
        }
        __syncthreads();

#pragma unroll
        for (int ks = 0; ks < BK / 8; ks++) {
            const int kk = ks * 8;
            u32 ahi[2][4], alo[2][4];
#pragma unroll
            for (int mi = 0; mi < 2; mi++) {
                const u32 off = (u32)(((warp_m * 32 + mi * 16 + a_row_in) * PAD
                                       + kk + a_kd) * 4);
                ldsm4(ahi[mi][0], ahi[mi][1], ahi[mi][2], ahi[mi][3], sAhi + off);
                ldsm4(alo[mi][0], alo[mi][1], alo[mi][2], alo[mi][3], sAlo + off);
            }
            u32 bhi[8][2], blo[8][2];
#pragma unroll
            for (int jp = 0; jp < 4; jp++) {
                const u32 off = (u32)(((warp_n * 64 + jp * 16 + b_row_in) * PAD
                                       + kk + b_kd) * 4);
                ldsm4(bhi[2 * jp][0], bhi[2 * jp][1],
                      bhi[2 * jp + 1][0], bhi[2 * jp + 1][1], sBhi + off);
                ldsm4(blo[2 * jp][0], blo[2 * jp][1],
                      blo[2 * jp + 1][0], blo[2 * jp + 1][1], sBlo + off);
            }
#pragma unroll
            for (int mi = 0; mi < 2; mi++)
#pragma unroll
                for (int j = 0; j < 8; j++) {
                    mma_tf32(acc[mi][j], alo[mi], bhi[j]);
                    mma_tf32(acc[mi][j], ahi[mi], blo[j]);
                    mma_tf32(acc[mi][j], ahi[mi], bhi[j]);
                }
        }
        __syncthreads();
    }

#pragma unroll
    for (int mi = 0; mi < 2; mi++) {
#pragma unroll
        for (int half = 0; half < 2; half++) {
            const int grow = row0 + warp_m * 32 + mi * 16 + g + half * 8;
            if (grow >= n_nodes) continue;
            if (ct < NUM_BASES) {
                float* p = g_proj + (size_t)grow * (NUM_BASES * FEAT) + ct * FEAT
                         + warp_n * 64 + 2 * tig;
#pragma unroll
                for (int j = 0; j < 8; j++)
                    *(float2*)(p + 8 * j) = make_float2(acc[mi][j][2 * half],
                                                        acc[mi][j][2 * half + 1]);
            } else {
                float* p = out + (size_t)grow * FEAT + warp_n * 64 + 2 * tig;
#pragma unroll
                for (int j = 0; j < 8; j++) {
                    const float2 b = *(const float2*)(bias + warp_n * 64 + 2 * tig + 8 * j);
                    *(float2*)(p + 8 * j) = make_float2(acc[mi][j][2 * half] + b.x,
                                                        acc[mi][j][2 * half + 1] + b.y);
                }
            }
        }
    }
}

// ---------------- kernel 2: warp-per-dst aggregation + fused ReLU ----------------
__global__ void rgcn_agg_kernel(const float* __restrict__ w_comp,
                                float* __restrict__ out, int n_nodes)
{
    const int node = (blockIdx.x * blockDim.x + threadIdx.x) >> 5;
    const int lane = threadIdx.x & 31;
    if (node >= n_nodes) return;

    const int beg = g_off[node];
    const int end = g_off[node + 1];

    float* __restrict__ o = out + (size_t)node * FEAT;
    float a0 = o[lane];
    float a1 = o[lane + 32];
    float a2 = o[lane + 64];
    float a3 = o[lane + 96];

    int e = beg;
    for (; e + 2 <= end; e += 2) {
        const int pk0 = g_pk[e], pk1 = g_pk[e + 1];
        const float4 c0 = *(const float4*)(w_comp + (pk0 & 7) * NUM_BASES);
        const float4 c1 = *(const float4*)(w_comp + (pk1 & 7) * NUM_BASES);
        const float* __restrict__ p0 = g_proj + (size_t)(pk0 >> 3) * (NUM_BASES * FEAT);
        const float* __restrict__ p1 = g_proj + (size_t)(pk1 >> 3) * (NUM_BASES * FEAT);
#pragma unroll
        for (int j = 0; j < 4; j++) {
            const int i = lane + j * 32;
            float m0 = c0.x * p0[i] + c0.y * p0[FEAT + i]
                     + c0.z * p0[2 * FEAT + i] + c0.w * p0[3 * FEAT + i];
            float m1 = c1.x * p1[i] + c1.y * p1[FEAT + i]
                     + c1.z * p1[2 * FEAT + i] + c1.w * p1[3 * FEAT + i];
            (&a0)[0] = a0;  // no-op to keep structure
            float add = m0 + m1;
            if (j == 0) a0 += add;
            else if (j == 1) a1 += add;
            else if (j == 2) a2 += add;
            else a3 += add;
        }
    }
    if (e < end) {
        const int pk = g_pk[e];
        const float4 c = *(const float4*)(w_comp + (pk & 7) * NUM_BASES);
        const float* __restrict__ p = g_proj + (size_t)(pk >> 3) * (NUM_BASES * FEAT);
#pragma unroll
        for (int j = 0; j < 4; j++) {
            const int i = lane + j * 32;
            float m = c.x * p[i] + c.y * p[FEAT + i]
                    + c.z * p[2 * FEAT + i] + c.w * p[3 * FEAT + i];
            if (j == 0) a0 += m;
            else if (j == 1) a1 += m;
            else if (j == 2) a2 += m;
            else a3 += m;
        }
    }

    o[lane]      = fmaxf(a0, 0.f);
    o[lane + 32] = fmaxf(a1, 0.f);
    o[lane + 64] = fmaxf(a2, 0.f);
    o[lane + 96] = fmaxf(a3, 0.f);
}

extern "C" void kernel_launch(void* const* d_in, const int* in_sizes, int n_in,
                              void* d_out, int out_size)
{
    const float* h      = (const float*)d_in[0];
    const float* weight = (const float*)d_in[1];
    const float* w_comp = (const float*)d_in[2];
    const float* root   = (const float*)d_in[3];
    const float* bias   = (const float*)d_in[4];
    const int*   src    = (const int*)d_in[5];
    const int*   dst    = (const int*)d_in[6];
    const int*   rel    = (const int*)d_in[7];

    const int n_nodes = in_sizes[0] / FEAT;
    const int n_edges = in_sizes[5];
    float* out = (float*)d_out;

    cudaFuncSetAttribute(rgcn_gemm_mma_kernel,
                         cudaFuncAttributeMaxDynamicSharedMemorySize, SM_TOTALB);

    // 0) weight transpose + dst-CSR build (all tiny, precede the big kernels)
    dim3 gt(4, 4, NCT);
    transpose_w_kernel<<<gt, dim3(32, 8)>>>(weight, root);
    zero_cnt_kernel<<<(n_nodes + 256) / 256, 256>>>(n_nodes);
    hist_kernel<<<(n_edges + 255) / 256, 256>>>(dst, n_edges);
    scan_kernel<<<1, 1024>>>(n_nodes + 1);
    scatter_kernel<<<(n_edges + 255) / 256, 256>>>(src, dst, rel, n_edges);

    // 1) split-TF32 tensor-core GEMM: proj (4 bases) + root+bias into out
    dim3 g1((n_nodes + 127) / 128, NCT);
    rgcn_gemm_mma_kernel<<<g1, 256, SM_TOTALB>>>(h, bias, out, n_nodes);

    // 2) warp-per-dst aggregation + fused ReLU (no atomics)
    int blocks_a = (n_nodes + 7) / 8;
    rgcn_agg_kernel<<<blocks_a, 256>>>(w_comp, out, n_nodes);
}

// round 9
// speedup vs baseline: 1.9962x; 1.9962x over previous
#include <cuda_runtime.h>
#include <cstdint>
#include <cstddef>

#define FEAT 128
#define NUM_BASES 4
#define NCT 5
#define MAX_NODES 100000

typedef unsigned int u32;

// scratch: basis projections + transposed weights
__device__ float g_proj[(size_t)MAX_NODES * NUM_BASES * FEAT];
__device__ float g_wt[NCT * FEAT * FEAT];   // [ct][n][k] = W_ct[k][n]

__device__ __forceinline__ u32 tf32r(float x) {
    u32 r; asm("cvt.rna.tf32.f32 %0, %1;" : "=r"(r) : "f"(x)); return r;
}
__device__ __forceinline__ void mma_tf32(float* d, const u32* a, const u32* b) {
    asm("mma.sync.aligned.m16n8k8.row.col.f32.tf32.tf32.f32 "
        "{%0,%1,%2,%3}, {%4,%5,%6,%7}, {%8,%9}, {%0,%1,%2,%3};"
        : "+f"(d[0]), "+f"(d[1]), "+f"(d[2]), "+f"(d[3])
        : "r"(a[0]), "r"(a[1]), "r"(a[2]), "r"(a[3]), "r"(b[0]), "r"(b[1]));
}
__device__ __forceinline__ u32 smem_u32(const void* p) {
    u32 a;
    asm("{ .reg .u64 t; cvta.to.shared.u64 t, %1; cvt.u32.u64 %0, t; }" : "=r"(a) : "l"(p));
    return a;
}
__device__ __forceinline__ void ldsm4(u32& r0, u32& r1, u32& r2, u32& r3, u32 addr) {
    asm volatile("ldmatrix.sync.aligned.m8n8.x4.shared.b16 {%0,%1,%2,%3}, [%4];"
                 : "=r"(r0), "=r"(r1), "=r"(r2), "=r"(r3) : "r"(addr));
}

// ---------------- kernel 0: transpose weights into g_wt ----------------
__global__ void transpose_w_kernel(const float* __restrict__ weight,
                                   const float* __restrict__ root)
{
    __shared__ float tile[32][33];
    const int ct = blockIdx.z;
    const float* __restrict__ src = (ct < NUM_BASES) ? (weight + (size_t)ct * FEAT * FEAT)
                                                     : root;
    const int n0 = blockIdx.x * 32, k0 = blockIdx.y * 32;
    const int tx = threadIdx.x, ty = threadIdx.y;  // 32 x 8
#pragma unroll
    for (int j = 0; j < 32; j += 8)
        tile[ty + j][tx] = src[(size_t)(k0 + ty + j) * FEAT + n0 + tx];
    __syncthreads();
    float* __restrict__ dst = g_wt + (size_t)ct * FEAT * FEAT;
#pragma unroll
    for (int j = 0; j < 32; j += 8)
        dst[(size_t)(n0 + ty + j) * FEAT + k0 + tx] = tile[tx][ty + j];
}

// ---------------- kernel 1: 2-term split-TF32 mma.sync GEMM ----------------
// C ~= Ahi*Bhi + Ahi*Blo  (A residual term dropped; rel err ~2e-4)
// Block computes 128 rows x 128 cols of column-tile ct = blockIdx.y:
//   ct 0..3 -> g_proj[:, ct, :],  ct 4 -> out = h@root + bias
#define BK 32
#define PAD 36
#define TILE_F (128 * PAD)
#define SM_TOTALB (3 * TILE_F * 4)   // Ahi,Bhi,Blo = 55296 B

__global__ void __launch_bounds__(256, 2)
rgcn_gemm_mma_kernel(const float* __restrict__ h,
                     const float* __restrict__ bias,
                     float* __restrict__ out, int n_nodes)
{
    extern __shared__ float smem[];
    float* As_hi = smem;
    float* Bs_hi = smem + TILE_F;
    float* Bs_lo = smem + 2 * TILE_F;

    const int tid  = threadIdx.x;
    const int lane = tid & 31;
    const int w    = tid >> 5;
    const int g    = lane >> 2;
    const int tig  = lane & 3;
    const int warp_m = w & 3;       // 4 warps in M: 32 rows each
    const int warp_n = w >> 2;      // 2 warps in N: 64 cols each

    const int ct   = blockIdx.y;
    const int row0 = blockIdx.x * 128;
    const float* __restrict__ Bsrc = g_wt + (size_t)ct * FEAT * FEAT;

    const int a_row_in = lane & 15;
    const int a_kd     = (lane >> 4) * 4;
    const int b_row_in = (lane & 7) + ((lane >> 4) << 3);
    const int b_kd     = ((lane & 15) >> 3) * 4;

    const u32 sAhi = smem_u32(As_hi);
    const u32 sBhi = smem_u32(Bs_hi), sBlo = smem_u32(Bs_lo);

    float acc[2][8][4];
#pragma unroll
    for (int mi = 0; mi < 2; mi++)
#pragma unroll
        for (int j = 0; j < 8; j++)
#pragma unroll
            for (int c = 0; c < 4; c++) acc[mi][j][c] = 0.f;

    for (int kc = 0; kc < FEAT; kc += BK) {
        // ---- producer: 128x32 tiles, 4 float4 per thread per matrix ----
#pragma unroll
        for (int i = 0; i < 4; i++) {
            const int v  = tid + i * 256;
            const int r  = v >> 3;         // 0..127
            const int c4 = (v & 7) * 4;    // 0..28
            // A: hi only (tf32-rounded)
            float4 av = make_float4(0.f, 0.f, 0.f, 0.f);
            const int gr = row0 + r;
            if (gr < n_nodes)
                av = *(const float4*)(h + (size_t)gr * FEAT + kc + c4);
            *(uint4*)(As_hi + r * PAD + c4) =
                make_uint4(tf32r(av.x), tf32r(av.y), tf32r(av.z), tf32r(av.w));
            // B: hi + residual
            float4 bv = *(const float4*)(Bsrc + (size_t)r * FEAT + kc + c4);
            u32 hi[4]; float lo[4];
#pragma unroll
            for (int e = 0; e < 4; e++) {
                float x = (&bv.x)[e];
                hi[e] = tf32r(x);
                lo[e] = x - __uint_as_float(hi[e]);
            }
            *(uint4*)(Bs_hi + r * PAD + c4) = make_uint4(hi[0], hi[1], hi[2], hi[3]);
            *(uint4*)(Bs_lo + r * PAD + c4) = make_uint4(tf32r(lo[0]), tf32r(lo[1]),
                                                         tf32r(lo[2]), tf32r(lo[3]));
        }
        __syncthreads();

#pragma unroll
        for (int ks = 0; ks < BK / 8; ks++) {
            const int kk = ks * 8;
            u32 ahi[2][4];
#pragma unroll
            for (int mi = 0; mi < 2; mi++) {
                const u32 off = (u32)(((warp_m * 32 + mi * 16 + a_row_in) * PAD
                                       + kk + a_kd) * 4);
                ldsm4(ahi[mi][0], ahi[mi][1], ahi[mi][2], ahi[mi][3], sAhi + off);
            }
            u32 bhi[8][2], blo[8][2];
#pragma unroll
            for (int jp = 0; jp < 4; jp++) {
                const u32 off = (u32)(((warp_n * 64 + jp * 16 + b_row_in) * PAD
                                       + kk + b_kd) * 4);
                ldsm4(bhi[2 * jp][0], bhi[2 * jp][1],
                      bhi[2 * jp + 1][0], bhi[2 * jp + 1][1], sBhi + off);
                ldsm4(blo[2 * jp][0], blo[2 * jp][1],
                      blo[2 * jp + 1][0], blo[2 * jp + 1][1], sBlo + off);
            }
#pragma unroll
            for (int mi = 0; mi < 2; mi++)
#pragma unroll
                for (int j = 0; j < 8; j++) {
                    mma_tf32(acc[mi][j], ahi[mi], blo[j]);
                    mma_tf32(acc[mi][j], ahi[mi], bhi[j]);
                }
        }
        __syncthreads();
    }

    // ---------------- epilogue ----------------
#pragma unroll
    for (int mi = 0; mi < 2; mi++) {
#pragma unroll
        for (int half = 0; half < 2; half++) {
            const int grow = row0 + warp_m * 32 + mi * 16 + g + half * 8;
            if (grow >= n_nodes) continue;
            if (ct < NUM_BASES) {
                float* p = g_proj + (size_t)grow * (NUM_BASES * FEAT) + ct * FEAT
                         + warp_n * 64 + 2 * tig;
#pragma unroll
                for (int j = 0; j < 8; j++)
                    *(float2*)(p + 8 * j) = make_float2(acc[mi][j][2 * half],
                                                        acc[mi][j][2 * half + 1]);
            } else {
                float* p = out + (size_t)grow * FEAT + warp_n * 64 + 2 * tig;
#pragma unroll
                for (int j = 0; j < 8; j++) {
                    const float2 b = *(const float2*)(bias + warp_n * 64 + 2 * tig + 8 * j);
                    *(float2*)(p + 8 * j) = make_float2(acc[mi][j][2 * half] + b.x,
                                                        acc[mi][j][2 * half + 1] + b.y);
                }
            }
        }
    }
}

// ---------------- kernel 2: edge gather/combine/scatter ----------------
__global__ void rgcn_edge_kernel(const float* __restrict__ w_comp,
                                 const int* __restrict__ src,
                                 const int* __restrict__ dst,
                                 const int* __restrict__ rel,
                                 float* __restrict__ out, int n_edges)
{
    const int warp = (blockIdx.x * blockDim.x + threadIdx.x) >> 5;
    const int lane = threadIdx.x & 31;
    if (warp >= n_edges) return;

    const int s = src[warp];
    const int d = dst[warp];
    const int r = rel[warp];
    const float4 c = *(const float4*)(w_comp + r * NUM_BASES);

    const float* __restrict__ p = g_proj + (size_t)s * (NUM_BASES * FEAT);
    float* __restrict__ o = out + (size_t)d * FEAT;

#pragma unroll
    for (int j = 0; j < 4; j++) {
        const int i = lane + j * 32;
        float m = c.x * p[i]
                + c.y * p[FEAT + i]
                + c.z * p[2 * FEAT + i]
                + c.w * p[3 * FEAT + i];
        atomicAdd(o + i, m);
    }
}

__global__ void rgcn_relu_kernel(float* __restrict__ out, int n4)
{
    int i = blockIdx.x * blockDim.x + threadIdx.x;
    if (i < n4) {
        float4 v = ((float4*)out)[i];
        v.x = fmaxf(v.x, 0.f); v.y = fmaxf(v.y, 0.f);
        v.z = fmaxf(v.z, 0.f); v.w = fmaxf(v.w, 0.f);
        ((float4*)out)[i] = v;
    }
}

extern "C" void kernel_launch(void* const* d_in, const int* in_sizes, int n_in,
                              void* d_out, int out_size)
{
    const float* h      = (const float*)d_in[0];
    const float* weight = (const float*)d_in[1];
    const float* w_comp = (const float*)d_in[2];
    const float* root   = (const float*)d_in[3];
    const float* bias   = (const float*)d_in[4];
    const int*   src    = (const int*)d_in[5];
    const int*   dst    = (const int*)d_in[6];
    const int*   rel    = (const int*)d_in[7];

    const int n_nodes = in_sizes[0] / FEAT;
    const int n_edges = in_sizes[5];
    float* out = (float*)d_out;

    cudaFuncSetAttribute(rgcn_gemm_mma_kernel,
                         cudaFuncAttributeMaxDynamicSharedMemorySize, SM_TOTALB);

    // 0) transpose weights (tiny)
    dim3 gt(4, 4, NCT);
    transpose_w_kernel<<<gt, dim3(32, 8)>>>(weight, root);

    // 1) 2-term split-TF32 tensor-core GEMM: proj (4 bases) + root+bias into out
    dim3 g1((n_nodes + 127) / 128, NCT);
    rgcn_gemm_mma_kernel<<<g1, 256, SM_TOTALB>>>(h, bias, out, n_nodes);

    // 2) edge combine + scatter-add
    int blocks_e = (n_edges + 7) / 8;
    rgcn_edge_kernel<<<blocks_e, 256>>>(w_comp, src, dst, rel, out, n_edges);

    // 3) ReLU
    int n4 = out_size / 4;
    rgcn_relu_kernel<<<(n4 + 255) / 256, 256>>>(out, n4);
}

// round 10
// speedup vs baseline: 2.3516x; 1.1781x over previous
#include <cuda_runtime.h>
#include <cuda_fp16.h>
#include <cstdint>
#include <cstddef>

#define FEAT 128
#define NUM_BASES 4
#define NCT 5
#define MAX_NODES 100000
#define PROJ_STRIDE (NUM_BASES * FEAT)   // 512 halfs per node

typedef unsigned int u32;

// scratch: fp16 basis projections (102 MB, fits L2) + transposed weights
__device__ __half g_projh[(size_t)MAX_NODES * PROJ_STRIDE];
__device__ float  g_wt[NCT * FEAT * FEAT];   // [ct][n][k] = W_ct[k][n]

__device__ __forceinline__ u32 tf32r(float x) {
    u32 r; asm("cvt.rna.tf32.f32 %0, %1;" : "=r"(r) : "f"(x)); return r;
}
__device__ __forceinline__ void mma_tf32(float* d, const u32* a, const u32* b) {
    asm("mma.sync.aligned.m16n8k8.row.col.f32.tf32.tf32.f32 "
        "{%0,%1,%2,%3}, {%4,%5,%6,%7}, {%8,%9}, {%0,%1,%2,%3};"
        : "+f"(d[0]), "+f"(d[1]), "+f"(d[2]), "+f"(d[3])
        : "r"(a[0]), "r"(a[1]), "r"(a[2]), "r"(a[3]), "r"(b[0]), "r"(b[1]));
}
__device__ __forceinline__ u32 smem_u32(const void* p) {
    u32 a;
    asm("{ .reg .u64 t; cvta.to.shared.u64 t, %1; cvt.u32.u64 %0, t; }" : "=r"(a) : "l"(p));
    return a;
}
__device__ __forceinline__ void ldsm4(u32& r0, u32& r1, u32& r2, u32& r3, u32 addr) {
    asm volatile("ldmatrix.sync.aligned.m8n8.x4.shared.b16 {%0,%1,%2,%3}, [%4];"
                 : "=r"(r0), "=r"(r1), "=r"(r2), "=r"(r3) : "r"(addr));
}

// ---------------- kernel 0: transpose weights into g_wt ----------------
__global__ void transpose_w_kernel(const float* __restrict__ weight,
                                   const float* __restrict__ root)
{
    __shared__ float tile[32][33];
    const int ct = blockIdx.z;
    const float* __restrict__ src = (ct < NUM_BASES) ? (weight + (size_t)ct * FEAT * FEAT)
                                                     : root;
    const int n0 = blockIdx.x * 32, k0 = blockIdx.y * 32;
    const int tx = threadIdx.x, ty = threadIdx.y;  // 32 x 8
#pragma unroll
    for (int j = 0; j < 32; j += 8)
        tile[ty + j][tx] = src[(size_t)(k0 + ty + j) * FEAT + n0 + tx];
    __syncthreads();
    float* __restrict__ dst = g_wt + (size_t)ct * FEAT * FEAT;
#pragma unroll
    for (int j = 0; j < 32; j += 8)
        dst[(size_t)(n0 + ty + j) * FEAT + k0 + tx] = tile[tx][ty + j];
}

// ---------------- kernel 1: 1xTF32 mma.sync GEMM ----------------
// C ~= tf32(A) * tf32(B); rel err ~3e-4.
// Block computes 128 rows x 128 cols of column-tile ct = blockIdx.y:
//   ct 0..3 -> g_projh[:, ct, :] (fp16),  ct 4 -> out = h@root + bias (fp32)
#define BK 32
#define PAD 36
#define TILE_F (128 * PAD)
#define SM_TOTALB (2 * TILE_F * 4)   // Ahi,Bhi = 36864 B

__global__ void __launch_bounds__(256, 2)
rgcn_gemm_mma_kernel(const float* __restrict__ h,
                     const float* __restrict__ bias,
                     float* __restrict__ out, int n_nodes)
{
    extern __shared__ float smem[];
    float* As_hi = smem;
    float* Bs_hi = smem + TILE_F;

    const int tid  = threadIdx.x;
    const int lane = tid & 31;
    const int w    = tid >> 5;
    const int g    = lane >> 2;
    const int tig  = lane & 3;
    const int warp_m = w & 3;       // 4 warps in M: 32 rows each
    const int warp_n = w >> 2;      // 2 warps in N: 64 cols each

    const int ct   = blockIdx.y;
    const int row0 = blockIdx.x * 128;
    const float* __restrict__ Bsrc = g_wt + (size_t)ct * FEAT * FEAT;

    const int a_row_in = lane & 15;
    const int a_kd     = (lane >> 4) * 4;
    const int b_row_in = (lane & 7) + ((lane >> 4) << 3);
    const int b_kd     = ((lane & 15) >> 3) * 4;

    const u32 sAhi = smem_u32(As_hi);
    const u32 sBhi = smem_u32(Bs_hi);

    float acc[2][8][4];
#pragma unroll
    for (int mi = 0; mi < 2; mi++)
#pragma unroll
        for (int j = 0; j < 8; j++)
#pragma unroll
            for (int c = 0; c < 4; c++) acc[mi][j][c] = 0.f;

    for (int kc = 0; kc < FEAT; kc += BK) {
        // ---- producer ----
#pragma unroll
        for (int i = 0; i < 4; i++) {
            const int v  = tid + i * 256;
            const int r  = v >> 3;         // 0..127
            const int c4 = (v & 7) * 4;    // 0..28
            float4 av = make_float4(0.f, 0.f, 0.f, 0.f);
            const int gr = row0 + r;
            if (gr < n_nodes)
                av = *(const float4*)(h + (size_t)gr * FEAT + kc + c4);
            *(uint4*)(As_hi + r * PAD + c4) =
                make_uint4(tf32r(av.x), tf32r(av.y), tf32r(av.z), tf32r(av.w));
            float4 bv = *(const float4*)(Bsrc + (size_t)r * FEAT + kc + c4);
            *(uint4*)(Bs_hi + r * PAD + c4) =
                make_uint4(tf32r(bv.x), tf32r(bv.y), tf32r(bv.z), tf32r(bv.w));
        }
        __syncthreads();

#pragma unroll
        for (int ks = 0; ks < BK / 8; ks++) {
            const int kk = ks * 8;
            u32 ahi[2][4];
#pragma unroll
            for (int mi = 0; mi < 2; mi++) {
                const u32 off = (u32)(((warp_m * 32 + mi * 16 + a_row_in) * PAD
                                       + kk + a_kd) * 4);
                ldsm4(ahi[mi][0], ahi[mi][1], ahi[mi][2], ahi[mi][3], sAhi + off);
            }
            u32 bhi[8][2];
#pragma unroll
            for (int jp = 0; jp < 4; jp++) {
                const u32 off = (u32)(((warp_n * 64 + jp * 16 + b_row_in) * PAD
                                       + kk + b_kd) * 4);
                ldsm4(bhi[2 * jp][0], bhi[2 * jp][1],
                      bhi[2 * jp + 1][0], bhi[2 * jp + 1][1], sBhi + off);
            }
#pragma unroll
            for (int mi = 0; mi < 2; mi++)
#pragma unroll
                for (int j = 0; j < 8; j++)
                    mma_tf32(acc[mi][j], ahi[mi], bhi[j]);
        }
        __syncthreads();
    }

    // ---------------- epilogue ----------------
#pragma unroll
    for (int mi = 0; mi < 2; mi++) {
#pragma unroll
        for (int half = 0; half < 2; half++) {
            const int grow = row0 + warp_m * 32 + mi * 16 + g + half * 8;
            if (grow >= n_nodes) continue;
            if (ct < NUM_BASES) {
                __half* p = g_projh + (size_t)grow * PROJ_STRIDE + ct * FEAT
                          + warp_n * 64 + 2 * tig;
#pragma unroll
                for (int j = 0; j < 8; j++)
                    *(__half2*)(p + 8 * j) =
                        __floats2half2_rn(acc[mi][j][2 * half], acc[mi][j][2 * half + 1]);
            } else {
                float* p = out + (size_t)grow * FEAT + warp_n * 64 + 2 * tig;
#pragma unroll
                for (int j = 0; j < 8; j++) {
                    const float2 b = *(const float2*)(bias + warp_n * 64 + 2 * tig + 8 * j);
                    *(float2*)(p + 8 * j) = make_float2(acc[mi][j][2 * half] + b.x,
                                                        acc[mi][j][2 * half + 1] + b.y);
                }
            }
        }
    }
}

// ---------------- kernel 2: edge gather/combine/scatter (fp16 proj) ----------------
// One warp per edge; lane covers feats [4*lane, 4*lane+4).
__global__ void rgcn_edge_kernel(const float* __restrict__ w_comp,
                                 const int* __restrict__ src,
                                 const int* __restrict__ dst,
                                 const int* __restrict__ rel,
                                 float* __restrict__ out, int n_edges)
{
    const int warp = (blockIdx.x * blockDim.x + threadIdx.x) >> 5;
    const int lane = threadIdx.x & 31;
    if (warp >= n_edges) return;

    const int s = src[warp];
    const int d = dst[warp];
    const int r = rel[warp];
    const float4 c = *(const float4*)(w_comp + r * NUM_BASES);

    const __half2* __restrict__ p =
        (const __half2*)(g_projh + (size_t)s * PROJ_STRIDE) + lane * 2;
    float m0 = 0.f, m1 = 0.f, m2 = 0.f, m3 = 0.f;
#pragma unroll
    for (int b = 0; b < 4; b++) {
        const float cb = (&c.x)[b];
        const float2 v0 = __half22float2(p[b * 64]);       // feats 4*lane, 4*lane+1
        const float2 v1 = __half22float2(p[b * 64 + 1]);   // feats 4*lane+2, +3
        m0 = fmaf(cb, v0.x, m0);
        m1 = fmaf(cb, v0.y, m1);
        m2 = fmaf(cb, v1.x, m2);
        m3 = fmaf(cb, v1.y, m3);
    }

    float* __restrict__ o = out + (size_t)d * FEAT + 4 * lane;
    atomicAdd(o + 0, m0);
    atomicAdd(o + 1, m1);
    atomicAdd(o + 2, m2);
    atomicAdd(o + 3, m3);
}

__global__ void rgcn_relu_kernel(float* __restrict__ out, int n4)
{
    int i = blockIdx.x * blockDim.x + threadIdx.x;
    if (i < n4) {
        float4 v = ((float4*)out)[i];
        v.x = fmaxf(v.x, 0.f); v.y = fmaxf(v.y, 0.f);
        v.z = fmaxf(v.z, 0.f); v.w = fmaxf(v.w, 0.f);
        ((float4*)out)[i] = v;
    }
}

extern "C" void kernel_launch(void* const* d_in, const int* in_sizes, int n_in,
                              void* d_out, int out_size)
{
    const float* h      = (const float*)d_in[0];
    const float* weight = (const float*)d_in[1];
    const float* w_comp = (const float*)d_in[2];
    const float* root   = (const float*)d_in[3];
    const float* bias   = (const float*)d_in[4];
    const int*   src    = (const int*)d_in[5];
    const int*   dst    = (const int*)d_in[6];
    const int*   rel    = (const int*)d_in[7];

    const int n_nodes = in_sizes[0] / FEAT;
    const int n_edges = in_sizes[5];
    float* out = (float*)d_out;

    cudaFuncSetAttribute(rgcn_gemm_mma_kernel,
                         cudaFuncAttributeMaxDynamicSharedMemorySize, SM_TOTALB);

    // 0) transpose weights (tiny)
    dim3 gt(4, 4, NCT);
    transpose_w_kernel<<<gt, dim3(32, 8)>>>(weight, root);

    // 1) 1xTF32 tensor-core GEMM: proj (4 bases, fp16) + root+bias into out
    dim3 g1((n_nodes + 127) / 128, NCT);
    rgcn_gemm_mma_kernel<<<g1, 256, SM_TOTALB>>>(h, bias, out, n_nodes);

    // 2) edge combine + scatter-add (fp16 gather, L2-resident)
    int blocks_e = (n_edges + 7) / 8;
    rgcn_edge_kernel<<<blocks_e, 256>>>(w_comp, src, dst, rel, out, n_edges);

    // 3) ReLU
    int n4 = out_size / 4;
    rgcn_relu_kernel<<<(n4 + 255) / 256, 256>>>(out, n4);
}

// round 11
// speedup vs baseline: 3.1402x; 1.3353x over previous
#include <cuda_runtime.h>
#include <cuda_fp16.h>
#include <cstdint>
#include <cstddef>

#define FEAT 128
#define NUM_BASES 4
#define NCT 5
#define MAX_NODES 100000
#define PROJ_STRIDE (NUM_BASES * FEAT)   // 512 halfs per node

typedef unsigned int u32;

// scratch: fp16 basis projections (102 MB, fits L2) + transposed weights
__device__ __half g_projh[(size_t)MAX_NODES * PROJ_STRIDE];
__device__ float  g_wt[NCT * FEAT * FEAT];   // [ct][n][k] = W_ct[k][n]

__device__ __forceinline__ u32 tf32r(float x) {
    u32 r; asm("cvt.rna.tf32.f32 %0, %1;" : "=r"(r) : "f"(x)); return r;
}
__device__ __forceinline__ void mma_tf32(float* d, const u32* a, const u32* b) {
    asm("mma.sync.aligned.m16n8k8.row.col.f32.tf32.tf32.f32 "
        "{%0,%1,%2,%3}, {%4,%5,%6,%7}, {%8,%9}, {%0,%1,%2,%3};"
        : "+f"(d[0]), "+f"(d[1]), "+f"(d[2]), "+f"(d[3])
        : "r"(a[0]), "r"(a[1]), "r"(a[2]), "r"(a[3]), "r"(b[0]), "r"(b[1]));
}
__device__ __forceinline__ u32 smem_u32(const void* p) {
    u32 a;
    asm("{ .reg .u64 t; cvta.to.shared.u64 t, %1; cvt.u32.u64 %0, t; }" : "=r"(a) : "l"(p));
    return a;
}
__device__ __forceinline__ void ldsm4(u32& r0, u32& r1, u32& r2, u32& r3, u32 addr) {
    asm volatile("ldmatrix.sync.aligned.m8n8.x4.shared.b16 {%0,%1,%2,%3}, [%4];"
                 : "=r"(r0), "=r"(r1), "=r"(r2), "=r"(r3) : "r"(addr));
}
__device__ __forceinline__ void red_add_v4(float* ptr, float a, float b, float c, float d) {
    asm volatile("red.global.add.v4.f32 [%0], {%1, %2, %3, %4};"
                 :: "l"(ptr), "f"(a), "f"(b), "f"(c), "f"(d) : "memory");
}

// ---------------- kernel 0: transpose weights into g_wt ----------------
__global__ void transpose_w_kernel(const float* __restrict__ weight,
                                   const float* __restrict__ root)
{
    __shared__ float tile[32][33];
    const int ct = blockIdx.z;
    const float* __restrict__ src = (ct < NUM_BASES) ? (weight + (size_t)ct * FEAT * FEAT)
                                                     : root;
    const int n0 = blockIdx.x * 32, k0 = blockIdx.y * 32;
    const int tx = threadIdx.x, ty = threadIdx.y;  // 32 x 8
#pragma unroll
    for (int j = 0; j < 32; j += 8)
        tile[ty + j][tx] = src[(size_t)(k0 + ty + j) * FEAT + n0 + tx];
    __syncthreads();
    float* __restrict__ dst = g_wt + (size_t)ct * FEAT * FEAT;
#pragma unroll
    for (int j = 0; j < 32; j += 8)
        dst[(size_t)(n0 + ty + j) * FEAT + k0 + tx] = tile[tx][ty + j];
}

// ---------------- kernel 1: 1xTF32 mma.sync GEMM ----------------
// Block computes 128 rows x 128 cols of column-tile ct = blockIdx.y:
//   ct 0..3 -> g_projh[:, ct, :] (fp16),  ct 4 -> out = h@root + bias (fp32)
#define BK 32
#define PAD 36
#define TILE_F (128 * PAD)
#define SM_TOTALB (2 * TILE_F * 4)   // 36864 B

__global__ void __launch_bounds__(256, 2)
rgcn_gemm_mma_kernel(const float* __restrict__ h,
                     const float* __restrict__ bias,
                     float* __restrict__ out, int n_nodes)
{
    extern __shared__ float smem[];
    float* As_hi = smem;
    float* Bs_hi = smem + TILE_F;

    const int tid  = threadIdx.x;
    const int lane = tid & 31;
    const int w    = tid >> 5;
    const int g    = lane >> 2;
    const int tig  = lane & 3;
    const int warp_m = w & 3;
    const int warp_n = w >> 2;

    const int ct   = blockIdx.y;
    const int row0 = blockIdx.x * 128;
    const float* __restrict__ Bsrc = g_wt + (size_t)ct * FEAT * FEAT;

    const int a_row_in = lane & 15;
    const int a_kd     = (lane >> 4) * 4;
    const int b_row_in = (lane & 7) + ((lane >> 4) << 3);
    const int b_kd     = ((lane & 15) >> 3) * 4;

    const u32 sAhi = smem_u32(As_hi);
    const u32 sBhi = smem_u32(Bs_hi);

    float acc[2][8][4];
#pragma unroll
    for (int mi = 0; mi < 2; mi++)
#pragma unroll
        for (int j = 0; j < 8; j++)
#pragma unroll
            for (int c = 0; c < 4; c++) acc[mi][j][c] = 0.f;

    for (int kc = 0; kc < FEAT; kc += BK) {
#pragma unroll
        for (int i = 0; i < 4; i++) {
            const int v  = tid + i * 256;
            const int r  = v >> 3;
            const int c4 = (v & 7) * 4;
            float4 av = make_float4(0.f, 0.f, 0.f, 0.f);
            const int gr = row0 + r;
            if (gr < n_nodes)
                av = *(const float4*)(h + (size_t)gr * FEAT + kc + c4);
            *(uint4*)(As_hi + r * PAD + c4) =
                make_uint4(tf32r(av.x), tf32r(av.y), tf32r(av.z), tf32r(av.w));
            float4 bv = *(const float4*)(Bsrc + (size_t)r * FEAT + kc + c4);
            *(uint4*)(Bs_hi + r * PAD + c4) =
                make_uint4(tf32r(bv.x), tf32r(bv.y), tf32r(bv.z), tf32r(bv.w));
        }
        __syncthreads();

#pragma unroll
        for (int ks = 0; ks < BK / 8; ks++) {
            const int kk = ks * 8;
            u32 ahi[2][4];
#pragma unroll
            for (int mi = 0; mi < 2; mi++) {
                const u32 off = (u32)(((warp_m * 32 + mi * 16 + a_row_in) * PAD
                                       + kk + a_kd) * 4);
                ldsm4(ahi[mi][0], ahi[mi][1], ahi[mi][2], ahi[mi][3], sAhi + off);
            }
            u32 bhi[8][2];
#pragma unroll
            for (int jp = 0; jp < 4; jp++) {
                const u32 off = (u32)(((warp_n * 64 + jp * 16 + b_row_in) * PAD
                                       + kk + b_kd) * 4);
                ldsm4(bhi[2 * jp][0], bhi[2 * jp][1],
                      bhi[2 * jp + 1][0], bhi[2 * jp + 1][1], sBhi + off);
            }
#pragma unroll
            for (int mi = 0; mi < 2; mi++)
#pragma unroll
                for (int j = 0; j < 8; j++)
                    mma_tf32(acc[mi][j], ahi[mi], bhi[j]);
        }
        __syncthreads();
    }

#pragma unroll
    for (int mi = 0; mi < 2; mi++) {
#pragma unroll
        for (int half = 0; half < 2; half++) {
            const int grow = row0 + warp_m * 32 + mi * 16 + g + half * 8;
            if (grow >= n_nodes) continue;
            if (ct < NUM_BASES) {
                __half* p = g_projh + (size_t)grow * PROJ_STRIDE + ct * FEAT
                          + warp_n * 64 + 2 * tig;
#pragma unroll
                for (int j = 0; j < 8; j++)
                    *(__half2*)(p + 8 * j) =
                        __floats2half2_rn(acc[mi][j][2 * half], acc[mi][j][2 * half + 1]);
            } else {
                float* p = out + (size_t)grow * FEAT + warp_n * 64 + 2 * tig;
#pragma unroll
                for (int j = 0; j < 8; j++) {
                    const float2 b = *(const float2*)(bias + warp_n * 64 + 2 * tig + 8 * j);
                    *(float2*)(p + 8 * j) = make_float2(acc[mi][j][2 * half] + b.x,
                                                        acc[mi][j][2 * half + 1] + b.y);
                }
            }
        }
    }
}

// ---------------- kernel 2: edge gather/combine/scatter (vector red) ----------------
// One warp per edge; lane covers feats [4*lane, 4*lane+4); one red.v4.f32 per lane.
__global__ void rgcn_edge_kernel(const float* __restrict__ w_comp,
                                 const int* __restrict__ src,
                                 const int* __restrict__ dst,
                                 const int* __restrict__ rel,
                                 float* __restrict__ out, int n_edges)
{
    const int warp = (blockIdx.x * blockDim.x + threadIdx.x) >> 5;
    const int lane = threadIdx.x & 31;
    if (warp >= n_edges) return;

    const int s = src[warp];
    const int d = dst[warp];
    const int r = rel[warp];
    const float4 c = *(const float4*)(w_comp + r * NUM_BASES);

    // 4 halfs (one per lane-chunk) per basis, loaded as 8B
    const uint2* __restrict__ p =
        (const uint2*)(g_projh + (size_t)s * PROJ_STRIDE) + lane;
    float m0 = 0.f, m1 = 0.f, m2 = 0.f, m3 = 0.f;
#pragma unroll
    for (int b = 0; b < 4; b++) {
        const float cb = (&c.x)[b];
        const uint2 raw = p[b * 32];                       // 4 halfs
        const float2 v0 = __half22float2(*(const __half2*)&raw.x);
        const float2 v1 = __half22float2(*(const __half2*)&raw.y);
        m0 = fmaf(cb, v0.x, m0);
        m1 = fmaf(cb, v0.y, m1);
        m2 = fmaf(cb, v1.x, m2);
        m3 = fmaf(cb, v1.y, m3);
    }

    red_add_v4(out + (size_t)d * FEAT + 4 * lane, m0, m1, m2, m3);
}

__global__ void rgcn_relu_kernel(float* __restrict__ out, int n4)
{
    int i = blockIdx.x * blockDim.x + threadIdx.x;
    if (i < n4) {
        float4 v = ((float4*)out)[i];
        v.x = fmaxf(v.x, 0.f); v.y = fmaxf(v.y, 0.f);
        v.z = fmaxf(v.z, 0.f); v.w = fmaxf(v.w, 0.f);
        ((float4*)out)[i] = v;
    }
}

extern "C" void kernel_launch(void* const* d_in, const int* in_sizes, int n_in,
                              void* d_out, int out_size)
{
    const float* h      = (const float*)d_in[0];
    const float* weight = (const float*)d_in[1];
    const float* w_comp = (const float*)d_in[2];
    const float* root   = (const float*)d_in[3];
    const float* bias   = (const float*)d_in[4];
    const int*   src    = (const int*)d_in[5];
    const int*   dst    = (const int*)d_in[6];
    const int*   rel    = (const int*)d_in[7];

    const int n_nodes = in_sizes[0] / FEAT;
    const int n_edges = in_sizes[5];
    float* out = (float*)d_out;

    cudaFuncSetAttribute(rgcn_gemm_mma_kernel,
                         cudaFuncAttributeMaxDynamicSharedMemorySize, SM_TOTALB);

    // 0) transpose weights (tiny)
    dim3 gt(4, 4, NCT);
    transpose_w_kernel<<<gt, dim3(32, 8)>>>(weight, root);

    // 1) 1xTF32 tensor-core GEMM: proj (4 bases, fp16) + root+bias into out
    dim3 g1((n_nodes + 127) / 128, NCT);
    rgcn_gemm_mma_kernel<<<g1, 256, SM_TOTALB>>>(h, bias, out, n_nodes);

    // 2) edge combine + vector scatter-add
    int blocks_e = (n_edges + 7) / 8;
    rgcn_edge_kernel<<<blocks_e, 256>>>(w_comp, src, dst, rel, out, n_edges);

    // 3) ReLU
    int n4 = out_size / 4;
    rgcn_relu_kernel<<<(n4 + 255) / 256, 256>>>(out, n4);
}

// round 12
// speedup vs baseline: 3.5751x; 1.1385x over previous
#include <cuda_runtime.h>
#include <cuda_fp16.h>
#include <cstdint>
#include <cstddef>

#define FEAT 128
#define NUM_BASES 4
#define NCT 5
#define MAX_NODES 100000
#define PROJ_STRIDE (NUM_BASES * FEAT)   // 512 halfs per node

typedef unsigned int u32;

// scratch: fp16 basis projections (102 MB, fits L2) + transposed fp16 weights
__device__ __half g_projh[(size_t)MAX_NODES * PROJ_STRIDE];
__device__ __half g_wth[NCT * FEAT * FEAT];   // [ct][n][k] = fp16(W_ct[k][n])

__device__ __forceinline__ void mma_f16(float* d, const u32* a, const u32* b) {
    asm("mma.sync.aligned.m16n8k16.row.col.f32.f16.f16.f32 "
        "{%0,%1,%2,%3}, {%4,%5,%6,%7}, {%8,%9}, {%0,%1,%2,%3};"
        : "+f"(d[0]), "+f"(d[1]), "+f"(d[2]), "+f"(d[3])
        : "r"(a[0]), "r"(a[1]), "r"(a[2]), "r"(a[3]), "r"(b[0]), "r"(b[1]));
}
__device__ __forceinline__ u32 smem_u32(const void* p) {
    u32 a;
    asm("{ .reg .u64 t; cvta.to.shared.u64 t, %1; cvt.u32.u64 %0, t; }" : "=r"(a) : "l"(p));
    return a;
}
__device__ __forceinline__ void ldsm4(u32& r0, u32& r1, u32& r2, u32& r3, u32 addr) {
    asm volatile("ldmatrix.sync.aligned.m8n8.x4.shared.b16 {%0,%1,%2,%3}, [%4];"
                 : "=r"(r0), "=r"(r1), "=r"(r2), "=r"(r3) : "r"(addr));
}
__device__ __forceinline__ void red_add_v4(float* ptr, float a, float b, float c, float d) {
    asm volatile("red.global.add.v4.f32 [%0], {%1, %2, %3, %4};"
                 :: "l"(ptr), "f"(a), "f"(b), "f"(c), "f"(d) : "memory");
}

// ---------------- kernel 0: transpose weights into fp16 g_wth ----------------
__global__ void transpose_w_kernel(const float* __restrict__ weight,
                                   const float* __restrict__ root)
{
    __shared__ float tile[32][33];
    const int ct = blockIdx.z;
    const float* __restrict__ src = (ct < NUM_BASES) ? (weight + (size_t)ct * FEAT * FEAT)
                                                     : root;
    const int n0 = blockIdx.x * 32, k0 = blockIdx.y * 32;
    const int tx = threadIdx.x, ty = threadIdx.y;  // 32 x 8
#pragma unroll
    for (int j = 0; j < 32; j += 8)
        tile[ty + j][tx] = src[(size_t)(k0 + ty + j) * FEAT + n0 + tx];
    __syncthreads();
    __half* __restrict__ dst = g_wth + (size_t)ct * FEAT * FEAT;
#pragma unroll
    for (int j = 0; j < 32; j += 8)
        dst[(size_t)(n0 + ty + j) * FEAT + k0 + tx] = __float2half_rn(tile[tx][ty + j]);
}

// ---------------- kernel 1: fp16 mma.sync (m16n8k16) GEMM ----------------
// Block computes 128 rows x 128 cols of column-tile ct = blockIdx.y:
//   ct 0..3 -> g_projh[:, ct, :] (fp16),  ct 4 -> out = h@root + bias (fp32)
#define BK 32
#define PADH 40                       // halfs per row (80 B, conflict-free ldmatrix)
#define TILE_H (128 * PADH)           // halfs per tile
#define SM_TOTALB (2 * TILE_H * 2)    // A + B fp16 tiles = 20480 B

__global__ void __launch_bounds__(256, 2)
rgcn_gemm_mma_kernel(const float* __restrict__ h,
                     const float* __restrict__ bias,
                     float* __restrict__ out, int n_nodes)
{
    extern __shared__ __half smemh[];
    __half* As = smemh;
    __half* Bs = smemh + TILE_H;

    const int tid  = threadIdx.x;
    const int lane = tid & 31;
    const int w    = tid >> 5;
    const int g    = lane >> 2;
    const int tig  = lane & 3;
    const int warp_m = w & 3;       // 4 warps in M: 32 rows each
    const int warp_n = w >> 2;      // 2 warps in N: 64 cols each

    const int ct   = blockIdx.y;
    const int row0 = blockIdx.x * 128;
    const __half* __restrict__ Bsrc = g_wth + (size_t)ct * FEAT * FEAT;

    // ldmatrix lane addressing: row within 16-block, k-half select
    const int l_row = lane & 15;
    const int l_kd  = (lane >> 4) * 8;    // 0 or 8 halfs

    const u32 sA = smem_u32(As);
    const u32 sB = smem_u32(Bs);

    float acc[2][8][4];
#pragma unroll
    for (int mi = 0; mi < 2; mi++)
#pragma unroll
        for (int j = 0; j < 8; j++)
#pragma unroll
            for (int c = 0; c < 4; c++) acc[mi][j][c] = 0.f;

    for (int kc = 0; kc < FEAT; kc += BK) {
        // ---- producer: 128x32 tiles, fp16; 4 float4 loads per thread per matrix ----
#pragma unroll
        for (int i = 0; i < 4; i++) {
            const int v  = tid + i * 256;
            const int r  = v >> 3;         // 0..127
            const int c4 = (v & 7) * 4;    // 0..28
            // A from h (fp32 -> fp16)
            float4 av = make_float4(0.f, 0.f, 0.f, 0.f);
            const int gr = row0 + r;
            if (gr < n_nodes)
                av = *(const float4*)(h + (size_t)gr * FEAT + kc + c4);
            __half2 a01 = __floats2half2_rn(av.x, av.y);
            __half2 a23 = __floats2half2_rn(av.z, av.w);
            *(uint2*)(As + r * PADH + c4) =
                make_uint2(*(u32*)&a01, *(u32*)&a23);
            // B already fp16 n-major
            *(uint2*)(Bs + r * PADH + c4) =
                *(const uint2*)(Bsrc + (size_t)r * FEAT + kc + c4);
        }
        __syncthreads();

#pragma unroll
        for (int ks = 0; ks < 2; ks++) {      // two k16 steps per kc
            const int kk = ks * 16;
            u32 af[2][4];
#pragma unroll
            for (int mi = 0; mi < 2; mi++) {
                const u32 off = (u32)(((warp_m * 32 + mi * 16 + l_row) * PADH
                                       + kk + l_kd) * 2);
                ldsm4(af[mi][0], af[mi][1], af[mi][2], af[mi][3], sA + off);
            }
            u32 bf[8][2];
#pragma unroll
            for (int jp = 0; jp < 4; jp++) {
                const u32 off = (u32)(((warp_n * 64 + jp * 16 + l_row) * PADH
                                       + kk + l_kd) * 2);
                u32 m0, m1, m2, m3;
                ldsm4(m0, m1, m2, m3, sB + off);
                bf[2 * jp][0] = m0;     bf[2 * jp][1] = m2;      // j: n rows 0-7
                bf[2 * jp + 1][0] = m1; bf[2 * jp + 1][1] = m3;  // j+1: n rows 8-15
            }
#pragma unroll
            for (int mi = 0; mi < 2; mi++)
#pragma unroll
                for (int j = 0; j < 8; j++)
                    mma_f16(acc[mi][j], af[mi], bf[j]);
        }
        __syncthreads();
    }

    // ---------------- epilogue ----------------
#pragma unroll
    for (int mi = 0; mi < 2; mi++) {
#pragma unroll
        for (int half = 0; half < 2; half++) {
            const int grow = row0 + warp_m * 32 + mi * 16 + g + half * 8;
            if (grow >= n_nodes) continue;
            if (ct < NUM_BASES) {
                __half* p = g_projh + (size_t)grow * PROJ_STRIDE + ct * FEAT
                          + warp_n * 64 + 2 * tig;
#pragma unroll
                for (int j = 0; j < 8; j++)
                    *(__half2*)(p + 8 * j) =
                        __floats2half2_rn(acc[mi][j][2 * half], acc[mi][j][2 * half + 1]);
            } else {
                float* p = out + (size_t)grow * FEAT + warp_n * 64 + 2 * tig;
#pragma unroll
                for (int j = 0; j < 8; j++) {
                    const float2 b = *(const float2*)(bias + warp_n * 64 + 2 * tig + 8 * j);
                    *(float2*)(p + 8 * j) = make_float2(acc[mi][j][2 * half] + b.x,
                                                        acc[mi][j][2 * half + 1] + b.y);
                }
            }
        }
    }
}

// ---------------- kernel 2: edge gather/combine/scatter (vector red) ----------------
__global__ void rgcn_edge_kernel(const float* __restrict__ w_comp,
                                 const int* __restrict__ src,
                                 const int* __restrict__ dst,
                                 const int* __restrict__ rel,
                                 float* __restrict__ out, int n_edges)
{
    const int warp = (blockIdx.x * blockDim.x + threadIdx.x) >> 5;
    const int lane = threadIdx.x & 31;
    if (warp >= n_edges) return;

    const int s = src[warp];
    const int d = dst[warp];
    const int r = rel[warp];
    const float4 c = *(const float4*)(w_comp + r * NUM_BASES);

    const uint2* __restrict__ p =
        (const uint2*)(g_projh + (size_t)s * PROJ_STRIDE) + lane;
    float m0 = 0.f, m1 = 0.f, m2 = 0.f, m3 = 0.f;
#pragma unroll
    for (int b = 0; b < 4; b++) {
        const float cb = (&c.x)[b];
        const uint2 raw = p[b * 32];
        const float2 v0 = __half22float2(*(const __half2*)&raw.x);
        const float2 v1 = __half22float2(*(const __half2*)&raw.y);
        m0 = fmaf(cb, v0.x, m0);
        m1 = fmaf(cb, v0.y, m1);
        m2 = fmaf(cb, v1.x, m2);
        m3 = fmaf(cb, v1.y, m3);
    }

    red_add_v4(out + (size_t)d * FEAT + 4 * lane, m0, m1, m2, m3);
}

__global__ void rgcn_relu_kernel(float* __restrict__ out, int n4)
{
    int i = blockIdx.x * blockDim.x + threadIdx.x;
    if (i < n4) {
        float4 v = ((float4*)out)[i];
        v.x = fmaxf(v.x, 0.f); v.y = fmaxf(v.y, 0.f);
        v.z = fmaxf(v.z, 0.f); v.w = fmaxf(v.w, 0.f);
        ((float4*)out)[i] = v;
    }
}

extern "C" void kernel_launch(void* const* d_in, const int* in_sizes, int n_in,
                              void* d_out, int out_size)
{
    const float* h      = (const float*)d_in[0];
    const float* weight = (const float*)d_in[1];
    const float* w_comp = (const float*)d_in[2];
    const float* root   = (const float*)d_in[3];
    const float* bias   = (const float*)d_in[4];
    const int*   src    = (const int*)d_in[5];
    const int*   dst    = (const int*)d_in[6];
    const int*   rel    = (const int*)d_in[7];

    const int n_nodes = in_sizes[0] / FEAT;
    const int n_edges = in_sizes[5];
    float* out = (float*)d_out;

    cudaFuncSetAttribute(rgcn_gemm_mma_kernel,
                         cudaFuncAttributeMaxDynamicSharedMemorySize, SM_TOTALB);

    // 0) transpose + fp16-convert weights (tiny)
    dim3 gt(4, 4, NCT);
    transpose_w_kernel<<<gt, dim3(32, 8)>>>(weight, root);

    // 1) fp16 tensor-core GEMM: proj (4 bases, fp16) + root+bias into out
    dim3 g1((n_nodes + 127) / 128, NCT);
    rgcn_gemm_mma_kernel<<<g1, 256, SM_TOTALB>>>(h, bias, out, n_nodes);

    // 2) edge combine + vector scatter-add
    int blocks_e = (n_edges + 7) / 8;
    rgcn_edge_kernel<<<blocks_e, 256>>>(w_comp, src, dst, rel, out, n_edges);

    // 3) ReLU
    int n4 = out_size / 4;
    rgcn_relu_kernel<<<(n4 + 255) / 256, 256>>>(out, n4);
}

// round 13
// speedup vs baseline: 3.8273x; 1.0705x over previous
#include <cuda_runtime.h>
#include <cuda_fp16.h>
#include <cstdint>
#include <cstddef>

#define FEAT 128
#define NUM_BASES 4
#define NCT 5
#define MAX_NODES 100000
#define PROJ_STRIDE (NUM_BASES * FEAT)   // 512 halfs per node

typedef unsigned int u32;

// scratch: fp16 basis projections (102 MB, fits L2) + transposed fp16 weights
__device__ __half g_projh[(size_t)MAX_NODES * PROJ_STRIDE];
__device__ __half g_wth[NCT * FEAT * FEAT];   // [ct][n][k] = fp16(W_ct[k][n])

__device__ __forceinline__ void mma_f16(float* d, const u32* a, const u32* b) {
    asm("mma.sync.aligned.m16n8k16.row.col.f32.f16.f16.f32 "
        "{%0,%1,%2,%3}, {%4,%5,%6,%7}, {%8,%9}, {%0,%1,%2,%3};"
        : "+f"(d[0]), "+f"(d[1]), "+f"(d[2]), "+f"(d[3])
        : "r"(a[0]), "r"(a[1]), "r"(a[2]), "r"(a[3]), "r"(b[0]), "r"(b[1]));
}
__device__ __forceinline__ u32 smem_u32(const void* p) {
    u32 a;
    asm("{ .reg .u64 t; cvta.to.shared.u64 t, %1; cvt.u32.u64 %0, t; }" : "=r"(a) : "l"(p));
    return a;
}
__device__ __forceinline__ void ldsm4(u32& r0, u32& r1, u32& r2, u32& r3, u32 addr) {
    asm volatile("ldmatrix.sync.aligned.m8n8.x4.shared.b16 {%0,%1,%2,%3}, [%4];"
                 : "=r"(r0), "=r"(r1), "=r"(r2), "=r"(r3) : "r"(addr));
}
__device__ __forceinline__ void red_add_v4(float* ptr, float a, float b, float c, float d) {
    asm volatile("red.global.add.v4.f32 [%0], {%1, %2, %3, %4};"
                 :: "l"(ptr), "f"(a), "f"(b), "f"(c), "f"(d) : "memory");
}
__device__ __forceinline__ void cpa16(u32 dst, const void* src) {
    asm volatile("cp.async.ca.shared.global [%0], [%1], 16;" :: "r"(dst), "l"(src));
}
#define CPA_COMMIT() asm volatile("cp.async.commit_group;" ::: "memory")
#define CPA_WAIT(n)  asm volatile("cp.async.wait_group %0;" :: "n"(n) : "memory")

// ---------------- kernel 0: transpose weights into fp16 g_wth ----------------
__global__ void transpose_w_kernel(const float* __restrict__ weight,
                                   const float* __restrict__ root)
{
    __shared__ float tile[32][33];
    const int ct = blockIdx.z;
    const float* __restrict__ src = (ct < NUM_BASES) ? (weight + (size_t)ct * FEAT * FEAT)
                                                     : root;
    const int n0 = blockIdx.x * 32, k0 = blockIdx.y * 32;
    const int tx = threadIdx.x, ty = threadIdx.y;  // 32 x 8
#pragma unroll
    for (int j = 0; j < 32; j += 8)
        tile[ty + j][tx] = src[(size_t)(k0 + ty + j) * FEAT + n0 + tx];
    __syncthreads();
    __half* __restrict__ dst = g_wth + (size_t)ct * FEAT * FEAT;
#pragma unroll
    for (int j = 0; j < 32; j += 8)
        dst[(size_t)(n0 + ty + j) * FEAT + k0 + tx] = __float2half_rn(tile[tx][ty + j]);
}

// ---------------- kernel 1: fp16 mma.sync GEMM, A-resident, ct-loop ----------------
// One block = 128 rows of h; loops ct = 0..4:
//   ct 0..3 -> g_projh[:, ct, :] (fp16),  ct 4 -> out = h@root + bias (fp32)
#define PADH 136                      // halfs per row (272 B; ldmatrix conflict-free)
#define TILE_H (128 * PADH)           // halfs per full-K tile
#define SM_TOTALB (3 * TILE_H * 2)    // A + 2 B buffers = 104448 B

__global__ void __launch_bounds__(256, 2)
rgcn_gemm_mma_kernel(const float* __restrict__ h,
                     const float* __restrict__ bias,
                     float* __restrict__ out, int n_nodes)
{
    extern __shared__ __half smemh[];
    __half* As = smemh;

    const int tid  = threadIdx.x;
    const int lane = tid & 31;
    const int w    = tid >> 5;
    const int g    = lane >> 2;
    const int tig  = lane & 3;
    const int warp_m = w & 3;       // 4 warps in M: 32 rows each
    const int warp_n = w >> 2;      // 2 warps in N: 64 cols each

    const int row0 = blockIdx.x * 128;

    const int l_row = lane & 15;
    const int l_kd  = (lane >> 4) * 8;    // 0 or 8 halfs

    const u32 sA = smem_u32(As);
    const u32 sB0 = sA + TILE_H * 2;      // buffer 0
    const u32 sB1 = sA + 2 * TILE_H * 2;  // buffer 1

    // ---- A producer: load h rows once, convert to fp16 ----
#pragma unroll
    for (int i = 0; i < 16; i++) {
        const int v  = tid + i * 256;
        const int r  = v >> 5;          // 0..127
        const int c4 = (v & 31) * 4;    // 0..124
        float4 av = make_float4(0.f, 0.f, 0.f, 0.f);
        const int gr = row0 + r;
        if (gr < n_nodes)
            av = *(const float4*)(h + (size_t)gr * FEAT + c4);
        __half2 a01 = __floats2half2_rn(av.x, av.y);
        __half2 a23 = __floats2half2_rn(av.z, av.w);
        *(uint2*)(As + r * PADH + c4) = make_uint2(*(u32*)&a01, *(u32*)&a23);
    }

    // ---- B prefetch: full-K fp16 tile for ct via cp.async ----
    auto issue_b = [&](int ct, u32 sBdst) {
        const __half* __restrict__ src = g_wth + (size_t)ct * FEAT * FEAT;
#pragma unroll
        for (int i = 0; i < 8; i++) {
            const int v  = tid + i * 256;
            const int r  = v >> 4;          // 0..127
            const int c8 = (v & 15) * 8;    // 0..120 halfs
            cpa16(sBdst + (u32)((r * PADH + c8) * 2), src + (size_t)r * FEAT + c8);
        }
        CPA_COMMIT();
    };

    issue_b(0, sB0);

    float acc[2][8][4];
#pragma unroll
    for (int mi = 0; mi < 2; mi++)
#pragma unroll
        for (int j = 0; j < 8; j++)
#pragma unroll
            for (int c = 0; c < 4; c++) acc[mi][j][c] = 0.f;

#pragma unroll 1
    for (int ct = 0; ct < NCT; ct++) {
        if (ct + 1 < NCT) {
            issue_b(ct + 1, ((ct + 1) & 1) ? sB1 : sB0);
            CPA_WAIT(1);
        } else {
            CPA_WAIT(0);
        }
        __syncthreads();
        const u32 sB = (ct & 1) ? sB1 : sB0;

#pragma unroll
        for (int ks = 0; ks < 8; ks++) {      // 8 k16 steps over K=128
            const int kk = ks * 16;
            u32 af[2][4];
#pragma unroll
            for (int mi = 0; mi < 2; mi++) {
                const u32 off = (u32)(((warp_m * 32 + mi * 16 + l_row) * PADH
                                       + kk + l_kd) * 2);
                ldsm4(af[mi][0], af[mi][1], af[mi][2], af[mi][3], sA + off);
            }
            u32 bf[8][2];
#pragma unroll
            for (int jp = 0; jp < 4; jp++) {
                const u32 off = (u32)(((warp_n * 64 + jp * 16 + l_row) * PADH
                                       + kk + l_kd) * 2);
                u32 m0, m1, m2, m3;
                ldsm4(m0, m1, m2, m3, sB + off);
                bf[2 * jp][0] = m0;     bf[2 * jp][1] = m2;
                bf[2 * jp + 1][0] = m1; bf[2 * jp + 1][1] = m3;
            }
#pragma unroll
            for (int mi = 0; mi < 2; mi++)
#pragma unroll
                for (int j = 0; j < 8; j++)
                    mma_f16(acc[mi][j], af[mi], bf[j]);
        }
        __syncthreads();   // protect B buffer (ct&1) before it is re-filled at ct+2

        // ---- epilogue for this ct ----
#pragma unroll
        for (int mi = 0; mi < 2; mi++) {
#pragma unroll
            for (int half = 0; half < 2; half++) {
                const int grow = row0 + warp_m * 32 + mi * 16 + g + half * 8;
                if (grow < n_nodes) {
                    if (ct < NUM_BASES) {
                        __half* p = g_projh + (size_t)grow * PROJ_STRIDE + ct * FEAT
                                  + warp_n * 64 + 2 * tig;
#pragma unroll
                        for (int j = 0; j < 8; j++)
                            *(__half2*)(p + 8 * j) =
                                __floats2half2_rn(acc[mi][j][2 * half],
                                                  acc[mi][j][2 * half + 1]);
                    } else {
                        float* p = out + (size_t)grow * FEAT + warp_n * 64 + 2 * tig;
#pragma unroll
                        for (int j = 0; j < 8; j++) {
                            const float2 b =
                                *(const float2*)(bias + warp_n * 64 + 2 * tig + 8 * j);
                            *(float2*)(p + 8 * j) =
                                make_float2(acc[mi][j][2 * half] + b.x,
                                            acc[mi][j][2 * half + 1] + b.y);
                        }
                    }
                }
            }
        }
#pragma unroll
        for (int mi = 0; mi < 2; mi++)
#pragma unroll
            for (int j = 0; j < 8; j++)
#pragma unroll
                for (int c = 0; c < 4; c++) acc[mi][j][c] = 0.f;
    }
}

// ---------------- kernel 2: edge gather/combine/scatter (vector red) ----------------
__global__ void rgcn_edge_kernel(const float* __restrict__ w_comp,
                                 const int* __restrict__ src,
                                 const int* __restrict__ dst,
                                 const int* __restrict__ rel,
                                 float* __restrict__ out, int n_edges)
{
    const int warp = (blockIdx.x * blockDim.x + threadIdx.x) >> 5;
    const int lane = threadIdx.x & 31;
    if (warp >= n_edges) return;

    const int s = src[warp];
    const int d = dst[warp];
    const int r = rel[warp];
    const float4 c = *(const float4*)(w_comp + r * NUM_BASES);

    const uint2* __restrict__ p =
        (const uint2*)(g_projh + (size_t)s * PROJ_STRIDE) + lane;
    float m0 = 0.f, m1 = 0.f, m2 = 0.f, m3 = 0.f;
#pragma unroll
    for (int b = 0; b < 4; b++) {
        const float cb = (&c.x)[b];
        const uint2 raw = p[b * 32];
        const float2 v0 = __half22float2(*(const __half2*)&raw.x);
        const float2 v1 = __half22float2(*(const __half2*)&raw.y);
        m0 = fmaf(cb, v0.x, m0);
        m1 = fmaf(cb, v0.y, m1);
        m2 = fmaf(cb, v1.x, m2);
        m3 = fmaf(cb, v1.y, m3);
    }

    red_add_v4(out + (size_t)d * FEAT + 4 * lane, m0, m1, m2, m3);
}

__global__ void rgcn_relu_kernel(float* __restrict__ out, int n4)
{
    int i = blockIdx.x * blockDim.x + threadIdx.x;
    if (i < n4) {
        float4 v = ((float4*)out)[i];
        v.x = fmaxf(v.x, 0.f); v.y = fmaxf(v.y, 0.f);
        v.z = fmaxf(v.z, 0.f); v.w = fmaxf(v.w, 0.f);
        ((float4*)out)[i] = v;
    }
}

extern "C" void kernel_launch(void* const* d_in, const int* in_sizes, int n_in,
                              void* d_out, int out_size)
{
    const float* h      = (const float*)d_in[0];
    const float* weight = (const float*)d_in[1];
    const float* w_comp = (const float*)d_in[2];
    const float* root   = (const float*)d_in[3];
    const float* bias   = (const float*)d_in[4];
    const int*   src    = (const int*)d_in[5];
    const int*   dst    = (const int*)d_in[6];
    const int*   rel    = (const int*)d_in[7];

    const int n_nodes = in_sizes[0] / FEAT;
    const int n_edges = in_sizes[5];
    float* out = (float*)d_out;

    cudaFuncSetAttribute(rgcn_gemm_mma_kernel,
                         cudaFuncAttributeMaxDynamicSharedMemorySize, SM_TOTALB);

    // 0) transpose + fp16-convert weights (tiny)
    dim3 gt(4, 4, NCT);
    transpose_w_kernel<<<gt, dim3(32, 8)>>>(weight, root);

    // 1) fp16 GEMM, A resident, loop over 5 weight matrices
    rgcn_gemm_mma_kernel<<<(n_nodes + 127) / 128, 256, SM_TOTALB>>>(h, bias, out, n_nodes);

    // 2) edge combine + vector scatter-add
    int blocks_e = (n_edges + 7) / 8;
    rgcn_edge_kernel<<<blocks_e, 256>>>(w_comp, src, dst, rel, out, n_edges);

    // 3) ReLU
    int n4 = out_size / 4;
    rgcn_relu_kernel<<<(n4 + 255) / 256, 256>>>(out, n4);
}